// round 11
// baseline (speedup 1.0000x reference)
#include <cuda_runtime.h>
#include <cstdint>

#define Bn 64
#define Tn 512
#define In 128
#define Hn 512
#define BTH (64*512*512)

// 64MB scratch for precomputed v_in = x @ W_in^T + b_in, layout [B*T, H]
__device__ float g_vin[BTH];

__device__ __forceinline__ uint32_t smem_u32(const void* p) {
    return (uint32_t)__cvta_generic_to_shared(p);
}

// Packed fp32x2 FMA (Blackwell FFMA2): d = a*b + d on both lanes, exact fp32.
__device__ __forceinline__ void ffma2(unsigned long long& d,
                                      unsigned long long a,
                                      unsigned long long b) {
    asm("fma.rn.f32x2 %0, %1, %2, %0;" : "+l"(d) : "l"(a), "l"(b));
}
__device__ __forceinline__ float hsum2(unsigned long long a) {
    float lo, hi;
    asm("mov.b64 {%0, %1}, %2;" : "=f"(lo), "=f"(hi) : "l"(a));
    return lo + hi;
}

__device__ __forceinline__ void mbar_init(uint32_t mbar, uint32_t cnt) {
    asm volatile("mbarrier.init.shared.b64 [%0], %1;" :: "r"(mbar), "r"(cnt) : "memory");
}
__device__ __forceinline__ void mbar_expect_tx(uint32_t mbar, uint32_t bytes) {
    asm volatile("mbarrier.arrive.expect_tx.shared.b64 _, [%0], %1;"
                 :: "r"(mbar), "r"(bytes) : "memory");
}
__device__ __forceinline__ void mbar_wait(uint32_t mbar, uint32_t parity) {
    asm volatile(
        "{\n\t.reg .pred P;\n\t"
        "WL_%=:\n\t"
        "mbarrier.try_wait.parity.acquire.cta.shared::cta.b64 P, [%0], %1, 0x989680;\n\t"
        "@!P bra WL_%=;\n\t}"
        :: "r"(mbar), "r"(parity) : "memory");
}
__device__ __forceinline__ uint32_t mapa_rk(uint32_t la, int rk) {
    uint32_t ra;
    asm("mapa.shared::cluster.u32 %0, %1, %2;" : "=r"(ra) : "r"(la), "r"(rk));
    return ra;
}
// Remote smem store that also delivers complete_tx to the remote mbarrier.
__device__ __forceinline__ void st_async_f32(uint32_t raddr, float v, uint32_t rmbar) {
    asm volatile("st.async.shared::cluster.mbarrier::complete_tx::bytes.f32 [%0], %1, [%2];"
                 :: "r"(raddr), "f"(v), "r"(rmbar) : "memory");
}

// ---------------------------------------------------------------------------
// Kernel 1: v_in GEMM.  g_vin[bt][h] = b_in[h] + sum_i x[bt][i] * W_in[h][i]
// ---------------------------------------------------------------------------
#define VIN_SMEM (2*128*132*4)

__global__ __launch_bounds__(256, 1)
void vin_gemm_kernel(const float* __restrict__ x,
                     const float* __restrict__ W_in,
                     const float* __restrict__ b_in) {
    extern __shared__ float sm[];
    float* xs = sm;             // [128 bt][132]
    float* ws = sm + 128*132;   // [128 k][132]

    const int row0 = blockIdx.x * 128;
    const int h0   = blockIdx.y * 128;

    for (int idx = threadIdx.x; idx < 128*32; idx += 256) {
        int r = idx >> 5, c4 = idx & 31;
        float4 v = *(const float4*)(x + (size_t)(row0 + r)*In + c4*4);
        *(float4*)(xs + r*132 + c4*4) = v;
        float4 w = *(const float4*)(W_in + (size_t)(h0 + r)*In + c4*4);
        ws[(c4*4 + 0)*132 + r] = w.x;
        ws[(c4*4 + 1)*132 + r] = w.y;
        ws[(c4*4 + 2)*132 + r] = w.z;
        ws[(c4*4 + 3)*132 + r] = w.w;
    }
    __syncthreads();

    const int ty = threadIdx.x >> 4;
    const int tx = threadIdx.x & 15;
    const int rb = ty * 8;
    const int cb = tx * 8;

    float acc[8][8];
    #pragma unroll
    for (int i = 0; i < 8; i++)
        #pragma unroll
        for (int j = 0; j < 8; j++) acc[i][j] = 0.f;

    #pragma unroll 2
    for (int k = 0; k < 128; ++k) {
        float a[8];
        #pragma unroll
        for (int i = 0; i < 8; i++) a[i] = xs[(rb + i)*132 + k];
        float bb[8];
        *(float4*)(bb)     = *(const float4*)(ws + k*132 + cb);
        *(float4*)(bb + 4) = *(const float4*)(ws + k*132 + cb + 4);
        #pragma unroll
        for (int i = 0; i < 8; i++) {
            float av = a[i];
            #pragma unroll
            for (int j = 0; j < 8; j++) acc[i][j] = fmaf(av, bb[j], acc[i][j]);
        }
    }

    float bias[8];
    *(float4*)(bias)     = *(const float4*)(b_in + h0 + cb);
    *(float4*)(bias + 4) = *(const float4*)(b_in + h0 + cb + 4);

    #pragma unroll
    for (int i = 0; i < 8; i++) {
        float* orow = g_vin + (size_t)(row0 + rb + i)*Hn + h0 + cb;
        float4 o0, o1;
        o0.x = acc[i][0] + bias[0]; o0.y = acc[i][1] + bias[1];
        o0.z = acc[i][2] + bias[2]; o0.w = acc[i][3] + bias[3];
        o1.x = acc[i][4] + bias[4]; o1.y = acc[i][5] + bias[5];
        o1.z = acc[i][6] + bias[6]; o1.w = acc[i][7] + bias[7];
        *(float4*)(orow)     = o0;
        *(float4*)(orow + 4) = o1;
    }
}

// ---------------------------------------------------------------------------
// Kernel 2: recurrence. 16 clusters x 8 CTAs, 512 thr, NO syncthreads in the
// steady state. Thread = (h = tid>>3, seg = tid&7): owns W_hid row
// (rank*64+h) cols [seg*64, +64) in regs; reduction over the 8 segs is a
// 3-level warp butterfly (the 8 partials live in one 8-lane group). Each
// lane fans out exactly 2 st.async (both batches of its group) to rank==seg.
// Intra-CTA ordering comes from the self-targeted st.async being counted in
// the 4096-B tx: a phase's mbar completion implies ALL local warps' reads of
// the previous buffer are done. expect_tx re-arm in warp 0 (whose own stores
// gate remote progress every half-step).
// fr layout per group: [2 slot][2 batch][8 seg][68] (4-float pad => the 8
// distinct LDS.128 addresses per warp hit disjoint banks).
//   smem: frA[2176] frB[2176] | 4 mbars
// ---------------------------------------------------------------------------
#define FRG_F   2176              // 2*2*544 floats per group
#define SEGP    68                // padded seg row
#define BROW    544               // 8*68, batch row
#define SLOTF   1088              // 2*544, slot size
#define MB_OFF  (2*FRG_F*4)
#define REC_SMEM (MB_OFF + 64)
#define TX_BYTES 4096u            // per dest per phase per group

struct GState { float v0, v1, vin0, vin1; unsigned ob0, ob1; };

template<bool DOWAIT, bool DOSIG>
__device__ __forceinline__ void half_step(
    const float* __restrict__ fb0,   // frg + RB*SLOTF + seg*SEGP (batch 0)
    uint32_t rfr0, uint32_t rfr1,    // remote dst addrs (slot WB) at rank seg
    uint32_t mb_wait, uint32_t sigr, int parity, bool rearm,
    const ulonglong2* w,
    GState& S, float al, float oma, float bias,
    float* __restrict__ out, int t, int seg)
{
    if (DOWAIT) {
        mbar_wait(mb_wait, (uint32_t)parity);
        if (rearm) mbar_expect_tx(mb_wait, TX_BYTES);   // warp0 only; its own
    }                                                   // stores follow in order
    const float* fb1 = fb0 + BROW;
    unsigned long long a0e = 0ull, a0o = 0ull, a1e = 0ull, a1o = 0ull;
    #pragma unroll
    for (int i = 0; i < 16; i++) {
        ulonglong2 f0 = *(const ulonglong2*)(fb0 + i*4);
        ulonglong2 f1 = *(const ulonglong2*)(fb1 + i*4);
        ffma2(a0e, w[i].x, f0.x); ffma2(a0o, w[i].y, f0.y);
        ffma2(a1e, w[i].x, f1.x); ffma2(a1o, w[i].y, f1.y);
    }
    float s0 = hsum2(a0e) + hsum2(a0o);
    float s1 = hsum2(a1e) + hsum2(a1o);
    // reduce over the 8 segs of this h (lanes 8k..8k+7)
    s0 += __shfl_xor_sync(0xffffffffu, s0, 1); s1 += __shfl_xor_sync(0xffffffffu, s1, 1);
    s0 += __shfl_xor_sync(0xffffffffu, s0, 2); s1 += __shfl_xor_sync(0xffffffffu, s1, 2);
    s0 += __shfl_xor_sync(0xffffffffu, s0, 4); s1 += __shfl_xor_sync(0xffffffffu, s1, 4);

    float vh0 = s0 + bias, vh1 = s1 + bias;
    float vn0 = oma*S.v0 + al*(vh0 + S.vin0);
    float vn1 = oma*S.v1 + al*(vh1 + S.vin1);
    S.v0 = vn0; S.v1 = vn1;
    float fn0 = fmaxf(vn0, 0.f), fn1 = fmaxf(vn1, 0.f);

    if (DOSIG) {
        st_async_f32(rfr0, fn0, sigr);
        st_async_f32(rfr1, fn1, sigr);
    }
    const unsigned ot0 = S.ob0, ot1 = S.ob1;
    if (seg == 0) {
        float vr0 = oma*vn0 + al*vh0;
        out[ot0] = fn0; out[BTH + ot0] = fmaxf(vr0, 0.f);
    } else if (seg == 1) {
        float vr1 = oma*vn1 + al*vh1;
        out[ot1] = fn1; out[BTH + ot1] = fmaxf(vr1, 0.f);
    }
    if (t + 1 < Tn) {
        S.vin0 = __ldg(g_vin + ot0 + Hn);
        S.vin1 = __ldg(g_vin + ot1 + Hn);
        S.ob0 = ot0 + Hn; S.ob1 = ot1 + Hn;
    }
}

__global__ __launch_bounds__(512, 1) __cluster_dims__(8, 1, 1)
void recur_kernel(const float* __restrict__ init_state,
                  const float* __restrict__ W_hid,
                  const float* __restrict__ b_hid,
                  const float* __restrict__ alpha,
                  float* __restrict__ out) {
    extern __shared__ float sm[];
    float* frA = sm;                 // [2][2][544]
    float* frB = sm + FRG_F;

    const int tid  = threadIdx.x;
    const int rank = blockIdx.x;     // cluster rank -> h slice
    const int clu  = blockIdx.y;
    const int hl   = tid >> 3;       // 0..63
    const int seg  = tid & 7;        // j segment AND fan-out dest rank

    const uint32_t smb   = smem_u32(sm);
    const uint32_t frA_u = smb;
    const uint32_t frB_u = smb + FRG_F*4;
    const uint32_t mbA0  = smb + MB_OFF;
    const uint32_t mbA1  = mbA0 + 8;
    const uint32_t mbB0  = mbA0 + 16;
    const uint32_t mbB1  = mbA0 + 24;

    // ---- W_hid slice into regs (row rank*64+hl, cols seg*64..+64) ----
    ulonglong2 w[16];
    {
        const float* wr = W_hid + (size_t)(rank*64 + hl)*Hn + seg*64;
        #pragma unroll
        for (int i = 0; i < 16; i++)
            w[i] = *(const ulonglong2*)(wr + i*4);
    }

    // ---- init slot-0 buffers with relu(init_state), padded layout ----
    for (int idx = tid; idx < 4*512; idx += 512) {
        int b4 = idx >> 9, j = idx & 511;
        float s = init_state[(size_t)(clu*4 + b4)*Hn + j];
        s = fmaxf(s, 0.f);
        float* dst = ((b4 < 2) ? frA : frB) + (b4 & 1)*BROW + (j >> 6)*SEGP + (j & 63);
        *dst = s;
    }

    // ---- mbarrier init + prologue arm ----
    if (tid == 0) {
        mbar_init(mbA0, 1); mbar_init(mbA1, 1);
        mbar_init(mbB0, 1); mbar_init(mbB1, 1);
        asm volatile("fence.mbarrier_init.release.cluster;" ::: "memory");
        mbar_expect_tx(mbA0, TX_BYTES); mbar_expect_tx(mbA1, TX_BYTES);
        mbar_expect_tx(mbB0, TX_BYTES); mbar_expect_tx(mbB1, TX_BYTES);
    }

    // ---- per-thread recurrence state (all 8 seg lanes replicate ew math) ----
    const int hg = rank*64 + hl;
    const float al   = alpha[hg];
    const float oma  = 1.f - al;
    const float bias = b_hid[hg];
    GState SA, SB;
    {
        const int bA0 = clu*4 + 0, bA1 = clu*4 + 1;
        const int bB0 = clu*4 + 2, bB1 = clu*4 + 3;
        SA.v0 = init_state[(size_t)bA0*Hn + hg];
        SA.v1 = init_state[(size_t)bA1*Hn + hg];
        SB.v0 = init_state[(size_t)bB0*Hn + hg];
        SB.v1 = init_state[(size_t)bB1*Hn + hg];
        SA.ob0 = (unsigned)(bA0*Tn*Hn + hg); SA.ob1 = (unsigned)(bA1*Tn*Hn + hg);
        SB.ob0 = (unsigned)(bB0*Tn*Hn + hg); SB.ob1 = (unsigned)(bB1*Tn*Hn + hg);
        SA.vin0 = __ldg(g_vin + SA.ob0); SA.vin1 = __ldg(g_vin + SA.ob1);
        SB.vin0 = __ldg(g_vin + SB.ob0); SB.vin1 = __ldg(g_vin + SB.ob1);
    }

    // ---- loop-invariant remote addresses (dest rank = seg; my h rows land
    //      in seg-row 'rank' of the destination's buffer) ----
    const uint32_t base_off = (uint32_t)(rank*SEGP + hl)*4u;
    const uint32_t rA_w1b0 = mapa_rk(frA_u + SLOTF*4 + base_off,          seg);
    const uint32_t rA_w1b1 = mapa_rk(frA_u + (SLOTF + BROW)*4 + base_off, seg);
    const uint32_t rA_w0b0 = mapa_rk(frA_u + base_off,                    seg);
    const uint32_t rA_w0b1 = mapa_rk(frA_u + BROW*4 + base_off,           seg);
    const uint32_t rB_w1b0 = mapa_rk(frB_u + SLOTF*4 + base_off,          seg);
    const uint32_t rB_w1b1 = mapa_rk(frB_u + (SLOTF + BROW)*4 + base_off, seg);
    const uint32_t rB_w0b0 = mapa_rk(frB_u + base_off,                    seg);
    const uint32_t rB_w0b1 = mapa_rk(frB_u + BROW*4 + base_off,           seg);
    const uint32_t sA0 = mapa_rk(mbA0, seg), sA1 = mapa_rk(mbA1, seg);
    const uint32_t sB0 = mapa_rk(mbB0, seg), sB1 = mapa_rk(mbB1, seg);

    const float* fbA0 = frA + seg*SEGP;            // slot0 read base, batch0
    const float* fbA1 = frA + SLOTF + seg*SEGP;    // slot1 read base
    const float* fbB0 = frB + seg*SEGP;
    const float* fbB1 = frB + SLOTF + seg*SEGP;

    const bool rearm = (tid == 0);

    __syncthreads();
    asm volatile("barrier.cluster.arrive.aligned;" ::: "memory");
    asm volatile("barrier.cluster.wait.aligned;"   ::: "memory");

    // ---- peeled u=0: t=0 no wait (prologue-filled buf0), t=1 waits parity 0
    half_step<false,true>(fbA0, rA_w1b0, rA_w1b1, mbA0, sA1, 0, rearm, w, SA, al, oma, bias, out, 0, seg);
    half_step<false,true>(fbB0, rB_w1b0, rB_w1b1, mbB0, sB1, 0, rearm, w, SB, al, oma, bias, out, 0, seg);
    half_step<true, true>(fbA1, rA_w0b0, rA_w0b1, mbA1, sA0, 0, rearm, w, SA, al, oma, bias, out, 1, seg);
    half_step<true, true>(fbB1, rB_w0b0, rB_w0b1, mbB1, sB0, 0, rearm, w, SB, al, oma, bias, out, 1, seg);

    #pragma unroll 1
    for (int u = 1; u < Tn/2 - 1; ++u) {
        const int p1 = u & 1, p0 = p1 ^ 1;
        const int t0 = 2*u, t1 = 2*u + 1;
        half_step<true,true>(fbA0, rA_w1b0, rA_w1b1, mbA0, sA1, p0, rearm, w, SA, al, oma, bias, out, t0, seg);
        half_step<true,true>(fbB0, rB_w1b0, rB_w1b1, mbB0, sB1, p0, rearm, w, SB, al, oma, bias, out, t0, seg);
        half_step<true,true>(fbA1, rA_w0b0, rA_w0b1, mbA1, sA0, p1, rearm, w, SA, al, oma, bias, out, t1, seg);
        half_step<true,true>(fbB1, rB_w0b0, rB_w0b1, mbB1, sB0, p1, rearm, w, SB, al, oma, bias, out, t1, seg);
    }

    // ---- final u = 255: t=511 skips the fan-out (nobody consumes it) ----
    {
        const int u = Tn/2 - 1;
        const int p1 = u & 1, p0 = p1 ^ 1;
        const int t0 = 2*u, t1 = 2*u + 1;
        half_step<true,true >(fbA0, rA_w1b0, rA_w1b1, mbA0, sA1, p0, rearm, w, SA, al, oma, bias, out, t0, seg);
        half_step<true,true >(fbB0, rB_w1b0, rB_w1b1, mbB0, sB1, p0, rearm, w, SB, al, oma, bias, out, t0, seg);
        half_step<true,false>(fbA1, rA_w0b0, rA_w0b1, mbA1, sA0, p1, rearm, w, SA, al, oma, bias, out, t1, seg);
        half_step<true,false>(fbB1, rB_w0b0, rB_w0b1, mbB1, sB0, p1, rearm, w, SB, al, oma, bias, out, t1, seg);
    }

    // No CTA may exit while a peer could still have remote stores in flight
    // toward its smem (exit deallocates smem -> fault).
    asm volatile("barrier.cluster.arrive.aligned;" ::: "memory");
    asm volatile("barrier.cluster.wait.aligned;"   ::: "memory");
}

// ---------------------------------------------------------------------------
extern "C" void kernel_launch(void* const* d_in, const int* in_sizes, int n_in,
                              void* d_out, int out_size) {
    const float* x          = (const float*)d_in[0];
    const float* init_state = (const float*)d_in[1];
    const float* W_in       = (const float*)d_in[2];
    const float* b_in       = (const float*)d_in[3];
    const float* W_hid      = (const float*)d_in[4];
    const float* b_hid      = (const float*)d_in[5];
    const float* alpha      = (const float*)d_in[6];
    float* out = (float*)d_out;

    cudaFuncSetAttribute(vin_gemm_kernel,
                         cudaFuncAttributeMaxDynamicSharedMemorySize, VIN_SMEM);
    cudaFuncSetAttribute(recur_kernel,
                         cudaFuncAttributeMaxDynamicSharedMemorySize, REC_SMEM);

    vin_gemm_kernel<<<dim3(Bn*Tn/128, Hn/128), 256, VIN_SMEM>>>(x, W_in, b_in);
    recur_kernel<<<dim3(8, Bn/4), 512, REC_SMEM>>>(init_state, W_hid, b_hid,
                                                   alpha, out);
}